// round 16
// baseline (speedup 1.0000x reference)
#include <cuda_runtime.h>
#include <cuda_fp16.h>
#include <math.h>

// Problem constants (fixed by the reference)
#define NB      2
#define NTOK    4096
#define DIM     512
#define HEADS   8
#define DH      64
#define NROWS   (NB * NTOK)          // 8192
#define ATT_SCALE 0.125f             // DH^-0.5
#define LOG2E   1.4426950408889634f

// -------- scratch (no allocs allowed -> __device__ globals) --------
__device__ __half g_qn [NROWS * DIM];
__device__ __half g_kvn[NROWS * DIM];
__device__ __half g_Q  [NROWS * DIM];
__device__ __half g_K  [NROWS * DIM];
__device__ __half g_V  [NROWS * DIM];
__device__ __half g_ctx[NROWS * DIM];
__device__ float  g_out[NROWS * DIM];
__device__ __half g_ln2[NROWS * DIM];
__device__ __half g_h1 [NROWS * DIM];
__device__ __half g_Wc [6 * 512 * 512];   // fp16, TRANSPOSED: [n][k]

// ---------------- helpers ----------------
__device__ __forceinline__ float ex2(float x) {
    float y;
    asm("ex2.approx.ftz.f32 %0, %1;" : "=f"(y) : "f"(x));
    return y;
}
__device__ __forceinline__ unsigned packh2(float lo, float hi) {
    __half2 h = __floats2half2_rn(lo, hi);
    return *(unsigned*)&h;
}

#define CPA(dst32, gsrc) asm volatile("cp.async.cg.shared.global [%0], [%1], 16;" :: "r"(dst32), "l"(gsrc))
#define CPC()  asm volatile("cp.async.commit_group;")
#define CPW(n) asm volatile("cp.async.wait_group %0;" :: "n"(n))

// D += A(16x16) * B(16x8), fp16 inputs, fp32 accumulate.
__device__ __forceinline__ void mma16(float* c, const unsigned* a, const unsigned* b) {
    asm volatile(
        "mma.sync.aligned.m16n8k16.row.col.f32.f16.f16.f32 "
        "{%0,%1,%2,%3}, {%4,%5,%6,%7}, {%8,%9}, {%0,%1,%2,%3};"
        : "+f"(c[0]), "+f"(c[1]), "+f"(c[2]), "+f"(c[3])
        : "r"(a[0]), "r"(a[1]), "r"(a[2]), "r"(a[3]), "r"(b[0]), "r"(b[1]));
}
__device__ __forceinline__ void ldsm2t(unsigned& r0, unsigned& r1, unsigned addr) {
    asm volatile("ldmatrix.sync.aligned.m8n8.x2.trans.shared.b16 {%0,%1}, [%2];"
                 : "=r"(r0), "=r"(r1) : "r"(addr));
}

// ======================= weight convert + transpose =======================
__global__ __launch_bounds__(256)
void wcvt_kernel(const float* __restrict__ w0, const float* __restrict__ w1,
                 const float* __restrict__ w2, const float* __restrict__ w3,
                 const float* __restrict__ w4, const float* __restrict__ w5,
                 __half* __restrict__ dst) {
    const float* srcs[6] = {w0, w1, w2, w3, w4, w5};
    const float* s = srcs[blockIdx.y];
    __half* d = dst + (size_t)blockIdx.y * 262144;
    int idx = blockIdx.x * 256 + threadIdx.x;     // 65536
    int n = idx & 511, k4 = (idx >> 9) * 4;
    __half2 h0 = __floats2half2_rn(s[(size_t)k4 * 512 + n], s[(size_t)(k4 + 1) * 512 + n]);
    __half2 h1 = __floats2half2_rn(s[(size_t)(k4 + 2) * 512 + n], s[(size_t)(k4 + 3) * 512 + n]);
    *(__half2*)(d + (size_t)n * 512 + k4)     = h0;
    *(__half2*)(d + (size_t)n * 512 + k4 + 2) = h1;
}

// ======================= LayerNorm (fp16 output) =======================
__global__ __launch_bounds__(128)
void ln_kernel(const float* __restrict__ x, const float* __restrict__ g,
               const float* __restrict__ bb, __half* __restrict__ y) {
    int row = blockIdx.x;
    const float* xr = x + (size_t)row * DIM;
    __half* yr = y + (size_t)row * DIM;
    int t = threadIdx.x;
    float v[4];
    float s = 0.f, s2 = 0.f;
#pragma unroll
    for (int i = 0; i < 4; i++) {
        float val = xr[t + 128 * i];
        v[i] = val; s += val; s2 += val * val;
    }
#pragma unroll
    for (int o = 16; o; o >>= 1) {
        s  += __shfl_xor_sync(0xffffffffu, s,  o);
        s2 += __shfl_xor_sync(0xffffffffu, s2, o);
    }
    __shared__ float rs[4], rs2[4];
    int w = t >> 5;
    if ((t & 31) == 0) { rs[w] = s; rs2[w] = s2; }
    __syncthreads();
    s  = rs[0] + rs[1] + rs[2] + rs[3];
    s2 = rs2[0] + rs2[1] + rs2[2] + rs2[3];
    float mean = s * (1.0f / DIM);
    float var  = s2 * (1.0f / DIM) - mean * mean;
    float rstd = rsqrtf(var + 1e-5f);
#pragma unroll
    for (int i = 0; i < 4; i++) {
        int c = t + 128 * i;
        yr[c] = __float2half_rn((v[i] - mean) * rstd * g[c] + bb[c]);
    }
}

// ======================= GEMM (fp16 mma, 3-stage cp.async, 8 warps) =========
// C[M,512] = A[M,512] @ W[512,512], W passed TRANSPOSED fp16 [n][k].
// BM=128 BN=128 BK=32, 256 thr = 8 warps (2x4), warp tile 64x32.
// Triple-buffered: load of tile k+2 covered by TWO compute phases.
#define G_SLOT 20480              // bytes per stage (A 10240 + B 10240)
#define GEMM_SMEM_BYTES (3 * G_SLOT)   // 61440
template<bool BIAS, bool RES, bool RELU, bool OUTH>
__global__ __launch_bounds__(256, 2)
void gemm_tc(const __half* __restrict__ A, const __half* __restrict__ Bt,
             const float* __restrict__ bias, const float* __restrict__ res,
             void* __restrict__ Cout, float oscale) {
    extern __shared__ char smc[];
    unsigned sbase = (unsigned)__cvta_generic_to_shared(smc);

    int t = threadIdx.x;
    int wid = t >> 5, lane = t & 31;
    int g = lane >> 2, tg = lane & 3;
    int wm = wid & 1, wn = wid >> 1;          // 2 x 4 warp grid
    int m0 = blockIdx.y * 128, n0 = blockIdx.x * 128;

    float acc[4][4][4];
#pragma unroll
    for (int mi = 0; mi < 4; mi++)
#pragma unroll
        for (int nj = 0; nj < 4; nj++)
#pragma unroll
            for (int q = 0; q < 4; q++) acc[mi][nj][q] = 0.f;

    auto stage = [&](int k0, int slot) {
#pragma unroll
        for (int l = 0; l < 2; l++) {       // A: 128 rows x 4 chunks(16B)
            int idx = t + 256 * l;
            int r = idx >> 2, c = idx & 3;
            CPA(sbase + slot * G_SLOT + (r * 40 + c * 8) * 2,
                A + (size_t)(m0 + r) * 512 + k0 + c * 8);
        }
#pragma unroll
        for (int l = 0; l < 2; l++) {       // Bt: 128 n-rows x 4 chunks
            int idx = t + 256 * l;
            int r = idx >> 2, c = idx & 3;
            CPA(sbase + slot * G_SLOT + 10240 + (r * 40 + c * 8) * 2,
                Bt + (size_t)(n0 + r) * 512 + k0 + c * 8);
        }
    };

    stage(0, 0); CPC();
    stage(32, 1); CPC();
    CPW(1);
    __syncthreads();

    for (int kt = 0; kt < 16; kt++) {
        int slot = kt % 3;
        if (kt < 14) { stage((kt + 2) * 32, (kt + 2) % 3); CPC(); }
        const __half* Asl = (const __half*)(smc + slot * G_SLOT);
        const __half* Bsl = (const __half*)(smc + slot * G_SLOT + 10240);
#pragma unroll
        for (int kb = 0; kb < 2; kb++) {
            unsigned a[4][4], b[4][2];
#pragma unroll
            for (int mi = 0; mi < 4; mi++) {
                int row = wm * 64 + mi * 16 + g;
                a[mi][0] = *(const unsigned*)(Asl + row * 40 + kb * 16 + 2 * tg);
                a[mi][1] = *(const unsigned*)(Asl + (row + 8) * 40 + kb * 16 + 2 * tg);
                a[mi][2] = *(const unsigned*)(Asl + row * 40 + kb * 16 + 2 * tg + 8);
                a[mi][3] = *(const unsigned*)(Asl + (row + 8) * 40 + kb * 16 + 2 * tg + 8);
            }
#pragma unroll
            for (int nj = 0; nj < 4; nj++) {
                int col = wn * 32 + nj * 8 + g;
                b[nj][0] = *(const unsigned*)(Bsl + col * 40 + kb * 16 + 2 * tg);
                b[nj][1] = *(const unsigned*)(Bsl + col * 40 + kb * 16 + 2 * tg + 8);
            }
#pragma unroll
            for (int mi = 0; mi < 4; mi++)
#pragma unroll
                for (int nj = 0; nj < 4; nj++)
                    mma16(acc[mi][nj], a[mi], b[nj]);
        }
        if (kt < 15) {
            if (kt == 14) { CPW(0); } else { CPW(1); }
            __syncthreads();
        }
    }

#pragma unroll
    for (int mi = 0; mi < 4; mi++) {
#pragma unroll
        for (int nj = 0; nj < 4; nj++) {
            int row = m0 + wm * 64 + mi * 16 + g;
            int col = n0 + wn * 32 + nj * 8 + tg * 2;
            float v0 = acc[mi][nj][0], v1 = acc[mi][nj][1];
            float v2 = acc[mi][nj][2], v3 = acc[mi][nj][3];
            if (BIAS) { float b0 = bias[col], b1 = bias[col + 1]; v0 += b0; v1 += b1; v2 += b0; v3 += b1; }
            if (RES)  { v0 += res[(size_t)row * 512 + col]; v1 += res[(size_t)row * 512 + col + 1];
                        v2 += res[(size_t)(row + 8) * 512 + col]; v3 += res[(size_t)(row + 8) * 512 + col + 1]; }
            if (RELU) { v0 = fmaxf(v0, 0.f); v1 = fmaxf(v1, 0.f); v2 = fmaxf(v2, 0.f); v3 = fmaxf(v3, 0.f); }
            if (OUTH) {
                __half* Ch = (__half*)Cout;
                *(__half2*)(Ch + (size_t)row * 512 + col)       = __floats2half2_rn(v0 * oscale, v1 * oscale);
                *(__half2*)(Ch + (size_t)(row + 8) * 512 + col) = __floats2half2_rn(v2 * oscale, v3 * oscale);
            } else {
                float* Cf = (float*)Cout;
                *(float2*)(Cf + (size_t)row * 512 + col)       = make_float2(v0, v1);
                *(float2*)(Cf + (size_t)(row + 8) * 512 + col) = make_float2(v2, v3);
            }
        }
    }
}

// ======================= Flash attention (fp16 mma, 3-stage, 8 warps) =======
// grid (NTOK/128, HEADS, NB), 256 threads = 8 warps, warp owns 16 q-rows.
// Q pre-scaled by ATT_SCALE*log2e; exp2 softmax without running max;
// per-thread partial l accumulated across tiles, quad-reduced once at end.
#define AT_SLOT 18432            // bytes per stage (K 9216 + V 9216)
#define A_QOFF  (3 * AT_SLOT)    // 55296
#define ATT_SMEM_BYTES (A_QOFF + 18432)   // 73728

__global__ __launch_bounds__(256, 2)
void attn_kernel(const __half* __restrict__ Q, const __half* __restrict__ Kp,
                 const __half* __restrict__ Vp, __half* __restrict__ O) {
    extern __shared__ char smc[];
    unsigned sbase = (unsigned)__cvta_generic_to_shared(smc);

    int b = blockIdx.z, h = blockIdx.y;
    int n0q = blockIdx.x * 128;
    int t = threadIdx.x;
    int wid = t >> 5, lane = t & 31;
    int g = lane >> 2, tg = lane & 3;
    int qb = wid * 16;                       // warp's 16 q-rows

    const __half* Qb = Q  + ((size_t)b * NTOK + n0q) * DIM + h * DH;
    const __half* Kb = Kp + (size_t)b * NTOK * DIM + h * DH;
    const __half* Vb = Vp + (size_t)b * NTOK * DIM + h * DH;

    auto stage_kv = [&](int m0, int slot) {
#pragma unroll
        for (int l = 0; l < 4; l++) {
            int idx = t + 256 * l;
            int tensor = idx >> 9;
            int rem = idx & 511;
            int r = rem >> 3, c = rem & 7;
            if (tensor == 0)
                CPA(sbase + slot * AT_SLOT + (r * 72 + c * 8) * 2,
                    Kb + (size_t)(m0 + r) * 512 + c * 8);
            else
                CPA(sbase + slot * AT_SLOT + 9216 + (r * 72 + c * 8) * 2,
                    Vb + (size_t)(m0 + r) * 512 + c * 8);
        }
    };

    // prologue: group0 = tile0 + Q, group1 = tile1
    stage_kv(0, 0);
#pragma unroll
    for (int l = 0; l < 4; l++) {
        int idx = t + 256 * l;
        int r = idx >> 3, c = idx & 7;
        CPA(sbase + A_QOFF + (r * 72 + c * 8) * 2, Qb + (size_t)r * 512 + c * 8);
    }
    CPC();
    stage_kv(64, 1); CPC();
    CPW(1);
    __syncthreads();

    const __half* Qs = (const __half*)(smc + A_QOFF);
    unsigned qa[4][4];
#pragma unroll
    for (int kb = 0; kb < 4; kb++) {
        int row = qb + g;
        qa[kb][0] = *(const unsigned*)(Qs + row * 72 + kb * 16 + 2 * tg);
        qa[kb][1] = *(const unsigned*)(Qs + (row + 8) * 72 + kb * 16 + 2 * tg);
        qa[kb][2] = *(const unsigned*)(Qs + row * 72 + kb * 16 + 2 * tg + 8);
        qa[kb][3] = *(const unsigned*)(Qs + (row + 8) * 72 + kb * 16 + 2 * tg + 8);
    }

    float o[8][4];
#pragma unroll
    for (int nj = 0; nj < 8; nj++)
#pragma unroll
        for (int q = 0; q < 4; q++) o[nj][q] = 0.f;
    float lp[2] = {0.f, 0.f};                // per-thread partial row sums

    const int NT = NTOK / 64;    // 64 key tiles
    for (int kt = 0; kt < NT; kt++) {
        int slot = kt % 3;
        if (kt < NT - 2) { stage_kv((kt + 2) * 64, (kt + 2) % 3); CPC(); }
        const __half* ks = (const __half*)(smc + slot * AT_SLOT);
        unsigned vsb = sbase + slot * AT_SLOT + 9216;

        // ---- S = Q K^T (16 x 64 per warp), log2 domain ----
        float s[8][4];
#pragma unroll
        for (int nj = 0; nj < 8; nj++)
#pragma unroll
            for (int q = 0; q < 4; q++) s[nj][q] = 0.f;
#pragma unroll
        for (int kb = 0; kb < 4; kb++)
#pragma unroll
            for (int nj = 0; nj < 8; nj++) {
                unsigned bq[2];
                bq[0] = *(const unsigned*)(ks + (nj * 8 + g) * 72 + kb * 16 + 2 * tg);
                bq[1] = *(const unsigned*)(ks + (nj * 8 + g) * 72 + kb * 16 + 2 * tg + 8);
                mma16(s[nj], qa[kb], bq);
            }

        // ---- max-free softmax: e = 2^s, per-thread partial l ----
        {
            float sum0 = 0.f, sum1 = 0.f;
#pragma unroll
            for (int nj = 0; nj < 8; nj++) {
                float e0 = ex2(s[nj][0]);
                float e1 = ex2(s[nj][1]);
                float e2 = ex2(s[nj][2]);
                float e3 = ex2(s[nj][3]);
                s[nj][0] = e0; s[nj][1] = e1; s[nj][2] = e2; s[nj][3] = e3;
                sum0 += e0 + e1;
                sum1 += e2 + e3;
            }
            lp[0] += sum0;
            lp[1] += sum1;
        }

        // ---- O += P V : A-frag = packed S C-frags; B-frag = LDSM.trans(V) ----
#pragma unroll
        for (int kb = 0; kb < 4; kb++) {
            unsigned pa[4];
            pa[0] = packh2(s[2 * kb][0],     s[2 * kb][1]);
            pa[1] = packh2(s[2 * kb][2],     s[2 * kb][3]);
            pa[2] = packh2(s[2 * kb + 1][0], s[2 * kb + 1][1]);
            pa[3] = packh2(s[2 * kb + 1][2], s[2 * kb + 1][3]);
            unsigned vrow = vsb + ((kb * 16 + (lane & 15)) * 72) * 2;
#pragma unroll
            for (int nj = 0; nj < 8; nj++) {
                unsigned bv0, bv1;
                ldsm2t(bv0, bv1, vrow + nj * 16);
                unsigned bv[2] = {bv0, bv1};
                mma16(o[nj], pa, bv);
            }
        }

        if (kt < NT - 1) {
            if (kt == NT - 2) { CPW(0); } else { CPW(1); }
            __syncthreads();
        }
    }

    // ---- final l reduction across the quad (cols split by tg) ----
#pragma unroll
    for (int half = 0; half < 2; half++) {
        lp[half] += __shfl_xor_sync(0xffffffffu, lp[half], 1);
        lp[half] += __shfl_xor_sync(0xffffffffu, lp[half], 2);
    }

    // ---- epilogue: 1/l, fp16 write (ctx feeds Wr GEMM) ----
    __half* Ob = O + ((size_t)b * NTOK + n0q) * DIM + h * DH;
    float il0 = 1.0f / lp[0];
    float il1 = 1.0f / lp[1];
    int r0 = qb + g;
#pragma unroll
    for (int nj = 0; nj < 8; nj++) {
        int col = nj * 8 + tg * 2;
        *(__half2*)(Ob + (size_t)r0 * 512 + col) =
            __floats2half2_rn(o[nj][0] * il0, o[nj][1] * il0);
        *(__half2*)(Ob + (size_t)(r0 + 8) * 512 + col) =
            __floats2half2_rn(o[nj][2] * il1, o[nj][3] * il1);
    }
}

// ======================= launcher =======================
extern "C" void kernel_launch(void* const* d_in, const int* in_sizes, int n_in,
                              void* d_out, int out_size) {
    const float* q0      = (const float*)d_in[0];
    const float* kv0     = (const float*)d_in[1];
    const float* normq_g = (const float*)d_in[2];
    const float* normq_b = (const float*)d_in[3];
    const float* normkv_g= (const float*)d_in[4];
    const float* normkv_b= (const float*)d_in[5];
    const float* Wq      = (const float*)d_in[6];
    const float* Wk      = (const float*)d_in[7];
    const float* Wv      = (const float*)d_in[8];
    const float* Wr      = (const float*)d_in[9];
    const float* mlp_g   = (const float*)d_in[10];
    const float* mlp_b   = (const float*)d_in[11];
    const float* W1      = (const float*)d_in[12];
    const float* b1      = (const float*)d_in[13];
    const float* W2      = (const float*)d_in[14];
    const float* b2      = (const float*)d_in[15];
    float* out = (float*)d_out;

    __half *qn, *kvn, *Qp, *Kp, *Vp, *ctx, *ln2, *h1, *Wc;
    float *outb;
    cudaGetSymbolAddress((void**)&qn,  g_qn);
    cudaGetSymbolAddress((void**)&kvn, g_kvn);
    cudaGetSymbolAddress((void**)&Qp,  g_Q);
    cudaGetSymbolAddress((void**)&Kp,  g_K);
    cudaGetSymbolAddress((void**)&Vp,  g_V);
    cudaGetSymbolAddress((void**)&ctx, g_ctx);
    cudaGetSymbolAddress((void**)&outb,g_out);
    cudaGetSymbolAddress((void**)&ln2, g_ln2);
    cudaGetSymbolAddress((void**)&h1,  g_h1);
    cudaGetSymbolAddress((void**)&Wc,  g_Wc);

    cudaFuncSetAttribute(gemm_tc<false,false,false,true>,  cudaFuncAttributeMaxDynamicSharedMemorySize, GEMM_SMEM_BYTES);
    cudaFuncSetAttribute(gemm_tc<false,true,false,false>,  cudaFuncAttributeMaxDynamicSharedMemorySize, GEMM_SMEM_BYTES);
    cudaFuncSetAttribute(gemm_tc<true,false,true,true>,    cudaFuncAttributeMaxDynamicSharedMemorySize, GEMM_SMEM_BYTES);
    cudaFuncSetAttribute(gemm_tc<true,true,false,false>,   cudaFuncAttributeMaxDynamicSharedMemorySize, GEMM_SMEM_BYTES);
    cudaFuncSetAttribute(attn_kernel, cudaFuncAttributeMaxDynamicSharedMemorySize, ATT_SMEM_BYTES);

    dim3 gemm_grid(512 / 128, NROWS / 128);   // (4, 64)

    // 0: convert + transpose weights to fp16 once per launch
    wcvt_kernel<<<dim3(256, 6), 256>>>(Wq, Wk, Wv, Wr, W1, W2, Wc);

    // 1-2: LayerNorms (fp16 outputs)
    ln_kernel<<<NROWS, 128>>>(q0,  normq_g,  normq_b,  qn);
    ln_kernel<<<NROWS, 128>>>(kv0, normkv_g, normkv_b, kvn);

    // 3-5: projections (fp16 outputs; Q pre-scaled by ATT_SCALE*log2e)
    gemm_tc<false,false,false,true><<<gemm_grid, 256, GEMM_SMEM_BYTES>>>(qn,  Wc + 0 * 262144, nullptr, nullptr, Qp, ATT_SCALE * LOG2E);
    gemm_tc<false,false,false,true><<<gemm_grid, 256, GEMM_SMEM_BYTES>>>(kvn, Wc + 1 * 262144, nullptr, nullptr, Kp, 1.0f);
    gemm_tc<false,false,false,true><<<gemm_grid, 256, GEMM_SMEM_BYTES>>>(kvn, Wc + 2 * 262144, nullptr, nullptr, Vp, 1.0f);

    // 6: attention (fp16 ctx output)
    dim3 att_grid(NTOK / 128, HEADS, NB);     // (32, 8, 2)
    attn_kernel<<<att_grid, 256, ATT_SMEM_BYTES>>>(Qp, Kp, Vp, ctx);

    // 7: out = ctx @ Wr + q0   (fp32 — feeds residual + LN)
    gemm_tc<false,true,false,false><<<gemm_grid, 256, GEMM_SMEM_BYTES>>>(ctx, Wc + 3 * 262144, nullptr, q0, outb, 1.0f);

    // 8: LN(out) (fp16)
    ln_kernel<<<NROWS, 128>>>(outb, mlp_g, mlp_b, ln2);

    // 9: h1 = relu(ln2 @ W1 + b1)  (fp16)
    gemm_tc<true,false,true,true><<<gemm_grid, 256, GEMM_SMEM_BYTES>>>(ln2, Wc + 4 * 262144, b1, nullptr, h1, 1.0f);

    // 10: final = h1 @ W2 + b2 + out  (fp32 -> d_out)
    gemm_tc<true,true,false,false><<<gemm_grid, 256, GEMM_SMEM_BYTES>>>(h1, Wc + 5 * 262144, b2, outb, out, 1.0f);
}